// round 4
// baseline (speedup 1.0000x reference)
#include <cuda_runtime.h>

// ---------------------------------------------------------------------------
// TEXTnetOrder2: fused multi-GEMM cell, fp32 SIMT, register-prefetch pipeline.
//
// Shapes: B=4096, I=1024, H=2048, O=256, M=100
// Output (concatenated): out[B,O] | new_hidden[B,H] | new_cell[B,H] | new_prev_hidden[B,H]
// ---------------------------------------------------------------------------

#define BM 128
#define BN 128
#define BK 16

// scratch (device-global: no allocations allowed)
static __device__ float g_ci[4096L * 2048];        // input @ W_ci^T + b_ci
static __device__ float g_midp[16L * 4096 * 128];  // split-K partials for mid GEMM

// AMODE: 0 = plain A[lda], 1 = concat(input,hidden,prev_hidden,cell), 2 = A + A2 + Avec[k]
// EPI:   0 = none, 1 = relu, 2 = tanh
// NGUARD: guard N (for N=100 tile)
// SPLIT:  split-K partial store (raw acc, no bias/epilogue), plane per blockIdx.z
template <int AMODE, int EPI, bool NGUARD, bool SPLIT>
__global__ __launch_bounds__(256, 2) void sgemm_k(
    int M, int N, int K, int kChunk,
    const float* __restrict__ A, int lda,
    const float* __restrict__ A2, const float* __restrict__ Avec,
    const float* __restrict__ Ain, const float* __restrict__ Ahid,
    const float* __restrict__ Aph, const float* __restrict__ Ace,
    const float* __restrict__ W, const float* __restrict__ bias,
    float* __restrict__ C, int ldc, long plane)
{
    __shared__ float As[BK][BM + 4];
    __shared__ float Bs[BK][BN + 4];

    const int tid = threadIdx.x;
    const int m0 = blockIdx.y * BM;
    const int n0 = blockIdx.x * BN;

    int kb = 0, ke = K;
    if (SPLIT) {
        kb = blockIdx.z * kChunk;
        ke = kb + kChunk;
        C += (long)blockIdx.z * plane;
    }

    const int ty8 = (tid >> 4) << 3;  // row base within tile (0..120)
    const int tx8 = (tid & 15) << 3;  // col base within tile (0..120)

    // per-thread load coords (2 chunks each for A and B tiles)
    // chunk it: idx = tid + it*256 -> row = idx>>2 (0..127), kc = (idx&3)<<2
    const int lrow0 = tid >> 2;
    const int lkc0 = (tid & 3) << 2;
    const int lrow1 = (tid + 256) >> 2;
    const int lkc1 = ((tid + 256) & 3) << 2;

    float acc[8][8];
#pragma unroll
    for (int i = 0; i < 8; ++i)
#pragma unroll
        for (int j = 0; j < 8; ++j) acc[i][j] = 0.f;

    // ---- tile fetch helpers (into registers) ----
    auto fetchA = [&](int kt, int row, int kc) -> float4 {
        int gm = m0 + row;
        int gk = kt + kc;
        if constexpr (AMODE == 0) {
            return *reinterpret_cast<const float4*>(A + (long)gm * lda + gk);
        } else if constexpr (AMODE == 1) {
            // concat segments: [0,1024) input, [1024,3072) hidden,
            // [3072,5120) prev_hidden, [5120,7168) cell. 16-aligned boundaries.
            const float* p;
            if (gk < 1024)        p = Ain  + (long)gm * 1024 + gk;
            else if (gk < 3072)   p = Ahid + (long)gm * 2048 + (gk - 1024);
            else if (gk < 5120)   p = Aph  + (long)gm * 2048 + (gk - 3072);
            else                  p = Ace  + (long)gm * 2048 + (gk - 5120);
            return *reinterpret_cast<const float4*>(p);
        } else {
            float4 x = *reinterpret_cast<const float4*>(A + (long)gm * lda + gk);
            float4 y = *reinterpret_cast<const float4*>(A2 + (long)gm * lda + gk);
            float4 z = *reinterpret_cast<const float4*>(Avec + gk);
            return make_float4(x.x + y.x + z.x, x.y + y.y + z.y,
                               x.z + y.z + z.z, x.w + y.w + z.w);
        }
    };
    auto fetchB = [&](int kt, int row, int kc) -> float4 {
        int gn = n0 + row;
        if (!NGUARD || gn < N)
            return *reinterpret_cast<const float4*>(W + (long)gn * K + kt + kc);
        return make_float4(0.f, 0.f, 0.f, 0.f);
    };

    // ---- prologue: prefetch first tile into registers ----
    float4 ra0 = fetchA(kb, lrow0, lkc0);
    float4 ra1 = fetchA(kb, lrow1, lkc1);
    float4 rb0 = fetchB(kb, lrow0, lkc0);
    float4 rb1 = fetchB(kb, lrow1, lkc1);

    for (int kt = kb; kt < ke; kt += BK) {
        // ---- store prefetched tile to smem ----
        As[lkc0 + 0][lrow0] = ra0.x; As[lkc0 + 1][lrow0] = ra0.y;
        As[lkc0 + 2][lrow0] = ra0.z; As[lkc0 + 3][lrow0] = ra0.w;
        As[lkc1 + 0][lrow1] = ra1.x; As[lkc1 + 1][lrow1] = ra1.y;
        As[lkc1 + 2][lrow1] = ra1.z; As[lkc1 + 3][lrow1] = ra1.w;
        Bs[lkc0 + 0][lrow0] = rb0.x; Bs[lkc0 + 1][lrow0] = rb0.y;
        Bs[lkc0 + 2][lrow0] = rb0.z; Bs[lkc0 + 3][lrow0] = rb0.w;
        Bs[lkc1 + 0][lrow1] = rb1.x; Bs[lkc1 + 1][lrow1] = rb1.y;
        Bs[lkc1 + 2][lrow1] = rb1.z; Bs[lkc1 + 3][lrow1] = rb1.w;
        __syncthreads();

        // ---- issue next-tile global loads (latency hidden by compute) ----
        int ktn = kt + BK;
        if (ktn < ke) {
            ra0 = fetchA(ktn, lrow0, lkc0);
            ra1 = fetchA(ktn, lrow1, lkc1);
            rb0 = fetchB(ktn, lrow0, lkc0);
            rb1 = fetchB(ktn, lrow1, lkc1);
        }

        // ---- compute ----
#pragma unroll
        for (int k = 0; k < BK; ++k) {
            float a[8], b[8];
            *reinterpret_cast<float4*>(&a[0]) = *reinterpret_cast<const float4*>(&As[k][ty8]);
            *reinterpret_cast<float4*>(&a[4]) = *reinterpret_cast<const float4*>(&As[k][ty8 + 4]);
            *reinterpret_cast<float4*>(&b[0]) = *reinterpret_cast<const float4*>(&Bs[k][tx8]);
            *reinterpret_cast<float4*>(&b[4]) = *reinterpret_cast<const float4*>(&Bs[k][tx8 + 4]);
#pragma unroll
            for (int i = 0; i < 8; ++i)
#pragma unroll
                for (int j = 0; j < 8; ++j) acc[i][j] += a[i] * b[j];
        }
        __syncthreads();
    }

    // ---- epilogue ----
    if constexpr (!SPLIT) {
        float bn[8];
#pragma unroll
        for (int j = 0; j < 8; ++j) {
            int gn = n0 + tx8 + j;
            bn[j] = (!NGUARD || gn < N) ? bias[gn] : 0.f;
        }
#pragma unroll
        for (int i = 0; i < 8; ++i) {
            long rowoff = (long)(m0 + ty8 + i) * ldc;
            if constexpr (!NGUARD) {
                float v[8];
#pragma unroll
                for (int j = 0; j < 8; ++j) {
                    float t = acc[i][j] + bn[j];
                    if constexpr (EPI == 1) t = fmaxf(t, 0.f);
                    if constexpr (EPI == 2) t = tanhf(t);
                    v[j] = t;
                }
                *reinterpret_cast<float4*>(&C[rowoff + n0 + tx8]) =
                    make_float4(v[0], v[1], v[2], v[3]);
                *reinterpret_cast<float4*>(&C[rowoff + n0 + tx8 + 4]) =
                    make_float4(v[4], v[5], v[6], v[7]);
            } else {
#pragma unroll
                for (int j = 0; j < 8; ++j) {
                    int gn = n0 + tx8 + j;
                    if (gn < N) {
                        float t = acc[i][j] + bn[j];
                        if constexpr (EPI == 1) t = fmaxf(t, 0.f);
                        if constexpr (EPI == 2) t = tanhf(t);
                        C[rowoff + gn] = t;
                    }
                }
            }
        }
    } else {
#pragma unroll
        for (int i = 0; i < 8; ++i) {
            long rowoff = (long)(m0 + ty8 + i) * ldc;
#pragma unroll
            for (int j = 0; j < 8; ++j) {
                int gn = n0 + tx8 + j;
                if (!NGUARD || gn < N) C[rowoff + gn] = acc[i][j];
            }
        }
    }
}

// out = relu(mid) @ W_mo^T + b_mo, where mid is reduced from split-K partials.
// One block = 8 rows; 256 threads = 256 output cols.
__global__ __launch_bounds__(256) void out_kernel(
    const float* __restrict__ midp,   // 16 planes of [4096,128]
    const float* __restrict__ b_cm2,  // [100]
    const float* __restrict__ Wmo,    // [256,100]
    const float* __restrict__ bmo,    // [256]
    float* __restrict__ out)          // [4096,256]
{
    const int r0 = blockIdx.x * 8;
    const int n = threadIdx.x;
    __shared__ float sm[8][100];

    for (int idx = n; idx < 800; idx += 256) {
        int r = idx / 100;
        int k = idx - r * 100;
        float s = b_cm2[k];
#pragma unroll
        for (int p = 0; p < 16; ++p)
            s += midp[(long)p * (4096L * 128) + (long)(r0 + r) * 128 + k];
        sm[r][k] = fmaxf(s, 0.f);  // relu(mid)
    }
    __syncthreads();

    float acc[8];
#pragma unroll
    for (int r = 0; r < 8; ++r) acc[r] = 0.f;
    for (int k = 0; k < 100; ++k) {
        float w = Wmo[n * 100 + k];
#pragma unroll
        for (int r = 0; r < 8; ++r) acc[r] += sm[r][k] * w;
    }
    float bb = bmo[n];
#pragma unroll
    for (int r = 0; r < 8; ++r) out[(long)(r0 + r) * 256 + n] = acc[r] + bb;
}

extern "C" void kernel_launch(void* const* d_in, const int* in_sizes, int n_in,
                              void* d_out, int out_size)
{
    const float* input = (const float*)d_in[0];
    const float* hidden = (const float*)d_in[1];
    const float* prevh = (const float*)d_in[2];
    const float* cell = (const float*)d_in[3];
    const float* W_ch2 = (const float*)d_in[4];
    const float* b_ch2 = (const float*)d_in[5];
    const float* W_cm2 = (const float*)d_in[6];
    const float* b_cm2 = (const float*)d_in[7];
    const float* W_mo = (const float*)d_in[8];
    const float* b_mo = (const float*)d_in[9];
    const float* W_ci = (const float*)d_in[10];
    const float* b_ci = (const float*)d_in[11];
    const float* W_ch = (const float*)d_in[12];
    const float* b_ch = (const float*)d_in[13];
    const float* W_fc = (const float*)d_in[14];
    const float* b_fc = (const float*)d_in[15];
    const float* vbias = (const float*)d_in[16];
    (void)in_sizes; (void)n_in; (void)out_size;

    float* out = (float*)d_out;
    float* out_o = out;                       // [4096,256]
    float* out_nh = out + 1048576;            // new_hidden  [4096,2048]
    float* out_nc = out_nh + 8388608;         // new_cell    [4096,2048]
    float* out_ph = out_nc + 8388608;         // new_prev_hidden (= h_proj)

    float* ci;
    float* midp;
    cudaGetSymbolAddress((void**)&ci, g_ci);
    cudaGetSymbolAddress((void**)&midp, g_midp);

    dim3 blk(256);

    // L1: new_hidden = concat @ W_ch2^T + b_ch2        (M=4096,N=2048,K=7168)
    sgemm_k<1, 0, false, false><<<dim3(16, 32), blk>>>(
        4096, 2048, 7168, 0, nullptr, 0, nullptr, nullptr,
        input, hidden, prevh, cell, W_ch2, b_ch2, out_nh, 2048, 0);

    // L2: mid partials = concat @ W_cm2^T (split-K=16) (M=4096,N=100,K=7168)
    sgemm_k<1, 0, true, true><<<dim3(1, 32, 16), blk>>>(
        4096, 100, 7168, 448, nullptr, 0, nullptr, nullptr,
        input, hidden, prevh, cell, W_cm2, nullptr, midp, 128, 4096L * 128);

    // L3: out = relu(mid) @ W_mo^T + b_mo              (reduces partials + bias + relu)
    out_kernel<<<512, 256>>>(midp, b_cm2, W_mo, b_mo, out_o);

    // L4: h_proj = new_hidden @ W_ch^T + b_ch  -> new_prev_hidden
    sgemm_k<0, 0, false, false><<<dim3(16, 32), blk>>>(
        4096, 2048, 2048, 0, out_nh, 2048, nullptr, nullptr,
        nullptr, nullptr, nullptr, nullptr, W_ch, b_ch, out_ph, 2048, 0);

    // L5: ci = input @ W_ci^T + b_ci
    sgemm_k<0, 0, false, false><<<dim3(16, 32), blk>>>(
        4096, 2048, 1024, 0, input, 1024, nullptr, nullptr,
        nullptr, nullptr, nullptr, nullptr, W_ci, b_ci, ci, 2048, 0);

    // L6: new_cell = tanh((ci + h_proj + bias) @ W_fc^T + b_fc)
    sgemm_k<2, 2, false, false><<<dim3(16, 32), blk>>>(
        4096, 2048, 2048, 0, ci, 2048, out_ph, vbias,
        nullptr, nullptr, nullptr, nullptr, W_fc, b_fc, out_nc, 2048, 0);
}

// round 9
// speedup vs baseline: 2.5642x; 2.5642x over previous
#include <cuda_runtime.h>
#include <cuda_bf16.h>
#include <cstdint>

// ---------------------------------------------------------------------------
// TEXTnetOrder2: all GEMMs via bf16x3 split (hi*hi + hi*lo + lo*hi) on
// mma.sync.m16n8k16 (HMMA, legal on compute_103 base target; tcgen05 is not).
// Shapes: B=4096, I=1024, H=2048, O=256, M=100.
// Output: out[B,256] | new_hidden[B,2048] | new_cell[B,2048] | new_prev_hidden[B,2048]
// ---------------------------------------------------------------------------

// ---- device scratch (no allocations allowed) ----
static __device__ __align__(128) float         g_midp[16L * 4096 * 128];  // split-K planes (mid GEMM)
static __device__ __align__(128) __nv_bfloat16 g_cat_hi[4096L * 7168], g_cat_lo[4096L * 7168];
static __device__ __align__(128) __nv_bfloat16 g_wch2_hi[2048L * 7168], g_wch2_lo[2048L * 7168];
static __device__ __align__(128) __nv_bfloat16 g_wcm2_hi[128L * 7168],  g_wcm2_lo[128L * 7168];  // padded 100->128
static __device__ __align__(128) __nv_bfloat16 g_wci_hi[2048L * 1024],  g_wci_lo[2048L * 1024];
static __device__ __align__(128) __nv_bfloat16 g_wch_hi[2048L * 2048],  g_wch_lo[2048L * 2048];
static __device__ __align__(128) __nv_bfloat16 g_wfc_hi[2048L * 2048],  g_wfc_lo[2048L * 2048];
static __device__ __align__(128) __nv_bfloat16 g_nh_hi[4096L * 2048],   g_nh_lo[4096L * 2048];
static __device__ __align__(128) __nv_bfloat16 g_lc_hi[4096L * 2048],   g_lc_lo[4096L * 2048];

__device__ __forceinline__ uint32_t s2u(const void* p) {
    uint32_t a;
    asm("{ .reg .u64 t; cvta.to.shared.u64 t, %1; cvt.u32.u64 %0, t; }" : "=r"(a) : "l"(p));
    return a;
}
#define CPA16(dst, src) \
    asm volatile("cp.async.cg.shared.global [%0], [%1], 16;" :: "r"(dst), "l"(src))

__device__ __forceinline__ void mma16816(float* d, const uint32_t* a, const uint32_t* b) {
    asm volatile(
        "mma.sync.aligned.m16n8k16.row.col.f32.bf16.bf16.f32 "
        "{%0,%1,%2,%3},{%4,%5,%6,%7},{%8,%9},{%0,%1,%2,%3};"
        : "+f"(d[0]), "+f"(d[1]), "+f"(d[2]), "+f"(d[3])
        : "r"(a[0]), "r"(a[1]), "r"(a[2]), "r"(a[3]), "r"(b[0]), "r"(b[1]));
}

__device__ __forceinline__ uint32_t pack_bf16x2(float x, float y) {
    __nv_bfloat162 t;
    t.x = __float2bfloat16(x);
    t.y = __float2bfloat16(y);
    return *reinterpret_cast<uint32_t*>(&t);
}
// split (v0,v1) into hi/lo bf16 pairs, store as packed u32
__device__ __forceinline__ void split2(float v0, float v1, uint32_t& hp, uint32_t& lp) {
    __nv_bfloat16 h0 = __float2bfloat16(v0), h1 = __float2bfloat16(v1);
    float l0 = v0 - __bfloat162float(h0), l1 = v1 - __bfloat162float(h1);
    __nv_bfloat162 hh; hh.x = h0; hh.y = h1;
    hp = *reinterpret_cast<uint32_t*>(&hh);
    lp = pack_bf16x2(l0, l1);
}

__device__ __forceinline__ void split_store4(float4 v, __nv_bfloat16* hi, __nv_bfloat16* lo, long idx) {
    __nv_bfloat16 h[4], l[4];
    float x[4] = {v.x, v.y, v.z, v.w};
#pragma unroll
    for (int i = 0; i < 4; ++i) {
        h[i] = __float2bfloat16(x[i]);
        l[i] = __float2bfloat16(x[i] - __bfloat162float(h[i]));
    }
    *reinterpret_cast<uint2*>(hi + idx) = *reinterpret_cast<const uint2*>(h);
    *reinterpret_cast<uint2*>(lo + idx) = *reinterpret_cast<const uint2*>(l);
}

// ---- conversion kernels (fp32 -> bf16 hi/lo) ----
__global__ __launch_bounds__(256) void conv_cat_k(
    const float* __restrict__ in, const float* __restrict__ hid,
    const float* __restrict__ ph, const float* __restrict__ ce,
    __nv_bfloat16* __restrict__ hi, __nv_bfloat16* __restrict__ lo)
{
    long g = (long)(blockIdx.x * 256 + threadIdx.x) * 4;
    int row = (int)(g / 7168), col = (int)(g % 7168);
    const float* p;
    if (col < 1024)      p = in  + (long)row * 1024 + col;
    else if (col < 3072) p = hid + (long)row * 2048 + (col - 1024);
    else if (col < 5120) p = ph  + (long)row * 2048 + (col - 3072);
    else                 p = ce  + (long)row * 2048 + (col - 5120);
    split_store4(*reinterpret_cast<const float4*>(p), hi, lo, g);
}

__global__ __launch_bounds__(256) void conv_w_k(
    const float* __restrict__ w, __nv_bfloat16* __restrict__ hi, __nv_bfloat16* __restrict__ lo)
{
    long g = (long)(blockIdx.x * 256 + threadIdx.x) * 4;
    split_store4(*reinterpret_cast<const float4*>(w + g), hi, lo, g);
}

// pad W_cm2 [100,7168] -> [128,7168] (zero rows 100..127)
__global__ __launch_bounds__(256) void conv_wpad_k(
    const float* __restrict__ w, __nv_bfloat16* __restrict__ hi, __nv_bfloat16* __restrict__ lo)
{
    long g = (long)(blockIdx.x * 256 + threadIdx.x) * 4;
    int row = (int)(g / 7168);
    float4 v = make_float4(0.f, 0.f, 0.f, 0.f);
    if (row < 100) v = *reinterpret_cast<const float4*>(w + g);
    split_store4(v, hi, lo, g);
}

// ---------------------------------------------------------------------------
// bf16x3 HMMA GEMM: C[M,N] = A[M,K] @ B[N,K]^T.
// CTA tile 128x128x32, 8 warps (4m x 2n), warp tile 32x64.
// EPI: 0 = C=acc+bias; 1 = EPI0 + hi/lo(C); 2 = hi/lo(acc+bias+Cadd+biasv), no C;
//      3 = C=tanh(acc+bias); 4 = raw split-K plane store
// smem stage (40960 B): Ahi[0,10240) Alo[10240) Bhi[20480) Blo[30720); row stride 80 B.
// ---------------------------------------------------------------------------
template <int EPI>
__global__ __launch_bounds__(256, 2) void hgemm_k(
    int K, int kChunk,
    const __nv_bfloat16* __restrict__ Ahi, const __nv_bfloat16* __restrict__ Alo, int lda,
    const __nv_bfloat16* __restrict__ Bhi, const __nv_bfloat16* __restrict__ Blo,
    const float* __restrict__ bias, const float* __restrict__ Cadd,
    const float* __restrict__ biasv,
    float* __restrict__ C, int ldc,
    __nv_bfloat16* __restrict__ Ohi, __nv_bfloat16* __restrict__ Olo, int ldo)
{
    extern __shared__ char smem[];
    const uint32_t sbase = s2u(smem);
    const int tid = threadIdx.x;
    const int wid = tid >> 5, lane = tid & 31;
    const int g = lane >> 2, tig = lane & 3;
    const int warp_m = wid >> 1, warp_n = wid & 1;
    const int m0 = blockIdx.y * 128, n0 = blockIdx.x * 128;
    const int kb = blockIdx.z * kChunk;
    if (EPI == 4) C += (long)blockIdx.z * (4096L * 128);

    float acc[2][8][4];
#pragma unroll
    for (int f = 0; f < 2; ++f)
#pragma unroll
        for (int j = 0; j < 8; ++j)
#pragma unroll
            for (int q = 0; q < 4; ++q) acc[f][j][q] = 0.f;

    auto issue = [&](int s, int kt) {
        const uint32_t st = sbase + (uint32_t)s * 40960u;
#pragma unroll
        for (int half = 0; half < 2; ++half) {
            int i = tid + half * 256;
            int r = i >> 2, c = i & 3;
            uint32_t dA = st + (uint32_t)(r * 80 + c * 16);
            long ga = (long)(m0 + r) * lda + kt + c * 8;
            CPA16(dA, Ahi + ga);
            CPA16(dA + 10240, Alo + ga);
            uint32_t dB = st + 20480u + (uint32_t)(r * 80 + c * 16);
            long gb = (long)(n0 + r) * (long)K + kt + c * 8;
            CPA16(dB, Bhi + gb);
            CPA16(dB + 10240, Blo + gb);
        }
        asm volatile("cp.async.commit_group;");
    };

    const int nt = kChunk / 32;
    issue(0, kb);

    for (int t = 0; t < nt; ++t) {
        if (t + 1 < nt) {
            issue((t + 1) & 1, kb + (t + 1) * 32);
            asm volatile("cp.async.wait_group 1;" ::: "memory");
        } else {
            asm volatile("cp.async.wait_group 0;" ::: "memory");
        }
        __syncthreads();

        const uint32_t st = sbase + (uint32_t)(t & 1) * 40960u;
        const uint32_t stA = st, stB = st + 20480u;

#pragma unroll
        for (int ks = 0; ks < 2; ++ks) {
            const int kbyte = ks * 32 + tig * 4;  // k elem = ks*16 + tig*2 -> bytes
            uint32_t aH[8], aL[8], b[16];

            // A hi fragments (2 m-frags x 4 regs)
#pragma unroll
            for (int f = 0; f < 2; ++f) {
                int r0 = warp_m * 32 + f * 16 + g;
                uint32_t base = stA + (uint32_t)(r0 * 80 + kbyte);
                aH[f * 4 + 0] = *(const uint32_t*)(smem + (base - sbase));
                aH[f * 4 + 1] = *(const uint32_t*)(smem + (base - sbase) + 8 * 80);
                aH[f * 4 + 2] = *(const uint32_t*)(smem + (base - sbase) + 16);
                aH[f * 4 + 3] = *(const uint32_t*)(smem + (base - sbase) + 8 * 80 + 16);
            }
            // B hi fragments (8 n-frags x 2 regs)
#pragma unroll
            for (int j = 0; j < 8; ++j) {
                int n = warp_n * 64 + j * 8 + g;
                uint32_t base = stB + (uint32_t)(n * 80 + kbyte);
                b[j * 2 + 0] = *(const uint32_t*)(smem + (base - sbase));
                b[j * 2 + 1] = *(const uint32_t*)(smem + (base - sbase) + 16);
            }
            // hh
#pragma unroll
            for (int f = 0; f < 2; ++f)
#pragma unroll
                for (int j = 0; j < 8; ++j) mma16816(acc[f][j], aH + f * 4, b + j * 2);

            // A lo fragments
#pragma unroll
            for (int f = 0; f < 2; ++f) {
                int r0 = warp_m * 32 + f * 16 + g;
                uint32_t base = stA + 10240u + (uint32_t)(r0 * 80 + kbyte);
                aL[f * 4 + 0] = *(const uint32_t*)(smem + (base - sbase));
                aL[f * 4 + 1] = *(const uint32_t*)(smem + (base - sbase) + 8 * 80);
                aL[f * 4 + 2] = *(const uint32_t*)(smem + (base - sbase) + 16);
                aL[f * 4 + 3] = *(const uint32_t*)(smem + (base - sbase) + 8 * 80 + 16);
            }
            // lh (aL * bH)
#pragma unroll
            for (int f = 0; f < 2; ++f)
#pragma unroll
                for (int j = 0; j < 8; ++j) mma16816(acc[f][j], aL + f * 4, b + j * 2);

            // B lo fragments (reuse b)
#pragma unroll
            for (int j = 0; j < 8; ++j) {
                int n = warp_n * 64 + j * 8 + g;
                uint32_t base = stB + 10240u + (uint32_t)(n * 80 + kbyte);
                b[j * 2 + 0] = *(const uint32_t*)(smem + (base - sbase));
                b[j * 2 + 1] = *(const uint32_t*)(smem + (base - sbase) + 16);
            }
            // hl (aH * bL)
#pragma unroll
            for (int f = 0; f < 2; ++f)
#pragma unroll
                for (int j = 0; j < 8; ++j) mma16816(acc[f][j], aH + f * 4, b + j * 2);
        }
        __syncthreads();
    }

    // ---- epilogue ----
#pragma unroll
    for (int f = 0; f < 2; ++f) {
#pragma unroll
        for (int j = 0; j < 8; ++j) {
            int row0 = m0 + warp_m * 32 + f * 16 + g;
            int col = n0 + warp_n * 64 + j * 8 + tig * 2;
#pragma unroll
            for (int h = 0; h < 2; ++h) {
                int row = row0 + h * 8;
                float v0 = acc[f][j][h * 2 + 0];
                float v1 = acc[f][j][h * 2 + 1];
                if constexpr (EPI == 4) {
                    *reinterpret_cast<float2*>(C + (long)row * ldc + col) = make_float2(v0, v1);
                } else {
                    float2 b2 = *reinterpret_cast<const float2*>(bias + col);
                    v0 += b2.x; v1 += b2.y;
                    if constexpr (EPI == 2) {
                        float2 a2 = *reinterpret_cast<const float2*>(Cadd + (long)row * 2048 + col);
                        float2 s2 = *reinterpret_cast<const float2*>(biasv + col);
                        v0 += a2.x + s2.x; v1 += a2.y + s2.y;
                        uint32_t hp, lp;
                        split2(v0, v1, hp, lp);
                        *reinterpret_cast<uint32_t*>(Ohi + (long)row * ldo + col) = hp;
                        *reinterpret_cast<uint32_t*>(Olo + (long)row * ldo + col) = lp;
                    } else if constexpr (EPI == 3) {
                        v0 = tanhf(v0); v1 = tanhf(v1);
                        *reinterpret_cast<float2*>(C + (long)row * ldc + col) = make_float2(v0, v1);
                    } else {
                        *reinterpret_cast<float2*>(C + (long)row * ldc + col) = make_float2(v0, v1);
                        if constexpr (EPI == 1) {
                            uint32_t hp, lp;
                            split2(v0, v1, hp, lp);
                            *reinterpret_cast<uint32_t*>(Ohi + (long)row * ldo + col) = hp;
                            *reinterpret_cast<uint32_t*>(Olo + (long)row * ldo + col) = lp;
                        }
                    }
                }
            }
        }
    }
}

// out = relu(mid) @ W_mo^T + b_mo; mid reduced from 16 split-K planes.
__global__ __launch_bounds__(256) void out_kernel(
    const float* __restrict__ midp, const float* __restrict__ b_cm2,
    const float* __restrict__ Wmo, const float* __restrict__ bmo,
    float* __restrict__ out)
{
    const int r0 = blockIdx.x * 8;
    const int n = threadIdx.x;
    __shared__ float sm[8][100];

    for (int idx = n; idx < 800; idx += 256) {
        int r = idx / 100;
        int k = idx - r * 100;
        float s = b_cm2[k];
#pragma unroll
        for (int p = 0; p < 16; ++p)
            s += midp[(long)p * (4096L * 128) + (long)(r0 + r) * 128 + k];
        sm[r][k] = fmaxf(s, 0.f);
    }
    __syncthreads();

    float acc[8];
#pragma unroll
    for (int r = 0; r < 8; ++r) acc[r] = 0.f;
    for (int k = 0; k < 100; ++k) {
        float w = Wmo[n * 100 + k];
#pragma unroll
        for (int r = 0; r < 8; ++r) acc[r] += sm[r][k] * w;
    }
    float bb = bmo[n];
#pragma unroll
    for (int r = 0; r < 8; ++r) out[(long)(r0 + r) * 256 + n] = acc[r] + bb;
}

// ---------------------------------------------------------------------------
extern "C" void kernel_launch(void* const* d_in, const int* in_sizes, int n_in,
                              void* d_out, int out_size)
{
    const float* input = (const float*)d_in[0];
    const float* hidden = (const float*)d_in[1];
    const float* prevh = (const float*)d_in[2];
    const float* cell = (const float*)d_in[3];
    const float* W_ch2 = (const float*)d_in[4];
    const float* b_ch2 = (const float*)d_in[5];
    const float* W_cm2 = (const float*)d_in[6];
    const float* b_cm2 = (const float*)d_in[7];
    const float* W_mo = (const float*)d_in[8];
    const float* b_mo = (const float*)d_in[9];
    const float* W_ci = (const float*)d_in[10];
    const float* b_ci = (const float*)d_in[11];
    const float* W_ch = (const float*)d_in[12];
    const float* b_ch = (const float*)d_in[13];
    const float* W_fc = (const float*)d_in[14];
    const float* b_fc = (const float*)d_in[15];
    const float* vbias = (const float*)d_in[16];
    (void)in_sizes; (void)n_in; (void)out_size;

    float* out = (float*)d_out;
    float* out_o = out;                  // [4096,256]
    float* out_nh = out + 1048576;       // new_hidden  [4096,2048]
    float* out_nc = out_nh + 8388608;    // new_cell    [4096,2048]
    float* out_ph = out_nc + 8388608;    // new_prev_hidden (= h_proj)

    float* midp;
    __nv_bfloat16 *cat_hi, *cat_lo, *wch2_hi, *wch2_lo, *wcm2_hi, *wcm2_lo;
    __nv_bfloat16 *wci_hi, *wci_lo, *wch_hi, *wch_lo, *wfc_hi, *wfc_lo;
    __nv_bfloat16 *nh_hi, *nh_lo, *lc_hi, *lc_lo;
    cudaGetSymbolAddress((void**)&midp, g_midp);
    cudaGetSymbolAddress((void**)&cat_hi, g_cat_hi);
    cudaGetSymbolAddress((void**)&cat_lo, g_cat_lo);
    cudaGetSymbolAddress((void**)&wch2_hi, g_wch2_hi);
    cudaGetSymbolAddress((void**)&wch2_lo, g_wch2_lo);
    cudaGetSymbolAddress((void**)&wcm2_hi, g_wcm2_hi);
    cudaGetSymbolAddress((void**)&wcm2_lo, g_wcm2_lo);
    cudaGetSymbolAddress((void**)&wci_hi, g_wci_hi);
    cudaGetSymbolAddress((void**)&wci_lo, g_wci_lo);
    cudaGetSymbolAddress((void**)&wch_hi, g_wch_hi);
    cudaGetSymbolAddress((void**)&wch_lo, g_wch_lo);
    cudaGetSymbolAddress((void**)&wfc_hi, g_wfc_hi);
    cudaGetSymbolAddress((void**)&wfc_lo, g_wfc_lo);
    cudaGetSymbolAddress((void**)&nh_hi, g_nh_hi);
    cudaGetSymbolAddress((void**)&nh_lo, g_nh_lo);
    cudaGetSymbolAddress((void**)&lc_hi, g_lc_hi);
    cudaGetSymbolAddress((void**)&lc_lo, g_lc_lo);

    const int SMEMSZ = 2 * 40960;  // 81920 B
    cudaFuncSetAttribute(hgemm_k<0>, cudaFuncAttributeMaxDynamicSharedMemorySize, SMEMSZ);
    cudaFuncSetAttribute(hgemm_k<1>, cudaFuncAttributeMaxDynamicSharedMemorySize, SMEMSZ);
    cudaFuncSetAttribute(hgemm_k<2>, cudaFuncAttributeMaxDynamicSharedMemorySize, SMEMSZ);
    cudaFuncSetAttribute(hgemm_k<3>, cudaFuncAttributeMaxDynamicSharedMemorySize, SMEMSZ);
    cudaFuncSetAttribute(hgemm_k<4>, cudaFuncAttributeMaxDynamicSharedMemorySize, SMEMSZ);

    // ---- conversions ----
    conv_cat_k<<<28672, 256>>>(input, hidden, prevh, cell, cat_hi, cat_lo);
    conv_w_k<<<14336, 256>>>(W_ch2, wch2_hi, wch2_lo);
    conv_wpad_k<<<896, 256>>>(W_cm2, wcm2_hi, wcm2_lo);
    conv_w_k<<<2048, 256>>>(W_ci, wci_hi, wci_lo);
    conv_w_k<<<4096, 256>>>(W_ch, wch_hi, wch_lo);
    conv_w_k<<<4096, 256>>>(W_fc, wfc_hi, wfc_lo);

    // L2: mid partials = concat @ W_cm2^T (split-K=16, N padded to 128)
    hgemm_k<4><<<dim3(1, 32, 16), 256, SMEMSZ>>>(
        7168, 448, cat_hi, cat_lo, 7168, wcm2_hi, wcm2_lo,
        nullptr, nullptr, nullptr, midp, 128, nullptr, nullptr, 0);

    // L3: out = relu(mid) @ W_mo^T + b_mo
    out_kernel<<<512, 256>>>(midp, b_cm2, W_mo, b_mo, out_o);

    // L1: new_hidden = concat @ W_ch2^T + b_ch2  (+ hi/lo for L4)
    hgemm_k<1><<<dim3(16, 32, 1), 256, SMEMSZ>>>(
        7168, 7168, cat_hi, cat_lo, 7168, wch2_hi, wch2_lo,
        b_ch2, nullptr, nullptr, out_nh, 2048, nh_hi, nh_lo, 2048);

    // L4: h_proj = new_hidden @ W_ch^T + b_ch -> new_prev_hidden
    hgemm_k<0><<<dim3(16, 32, 1), 256, SMEMSZ>>>(
        2048, 2048, nh_hi, nh_lo, 2048, wch_hi, wch_lo,
        b_ch, nullptr, nullptr, out_ph, 2048, nullptr, nullptr, 0);

    // L5: lc = input @ W_ci^T + b_ci + h_proj + bias  (hi/lo only; A = first 1024 cols of concat)
    hgemm_k<2><<<dim3(16, 32, 1), 256, SMEMSZ>>>(
        1024, 1024, cat_hi, cat_lo, 7168, wci_hi, wci_lo,
        b_ci, out_ph, vbias, nullptr, 0, lc_hi, lc_lo, 2048);

    // L6: new_cell = tanh(lc @ W_fc^T + b_fc)
    hgemm_k<3><<<dim3(16, 32, 1), 256, SMEMSZ>>>(
        2048, 2048, lc_hi, lc_lo, 2048, wfc_hi, wfc_lo,
        b_fc, nullptr, nullptr, out_nc, 2048, nullptr, nullptr, 0);
}

// round 11
// speedup vs baseline: 2.5746x; 1.0041x over previous
#include <cuda_runtime.h>
#include <cuda_bf16.h>
#include <cstdint>

// ---------------------------------------------------------------------------
// TEXTnetOrder2: all GEMMs via bf16x3 split (hi*hi + hi*lo + lo*hi) on
// mma.sync.m16n8k16 (HMMA). R10: L2-locality CTA swizzle (GM=16 supergroups).
// Shapes: B=4096, I=1024, H=2048, O=256, M=100.
// Output: out[B,256] | new_hidden[B,2048] | new_cell[B,2048] | new_prev_hidden[B,2048]
// ---------------------------------------------------------------------------

// ---- device scratch (no allocations allowed) ----
static __device__ __align__(128) float         g_midp[16L * 4096 * 128];  // split-K planes (mid GEMM)
static __device__ __align__(128) __nv_bfloat16 g_cat_hi[4096L * 7168], g_cat_lo[4096L * 7168];
static __device__ __align__(128) __nv_bfloat16 g_wch2_hi[2048L * 7168], g_wch2_lo[2048L * 7168];
static __device__ __align__(128) __nv_bfloat16 g_wcm2_hi[128L * 7168],  g_wcm2_lo[128L * 7168];  // padded 100->128
static __device__ __align__(128) __nv_bfloat16 g_wci_hi[2048L * 1024],  g_wci_lo[2048L * 1024];
static __device__ __align__(128) __nv_bfloat16 g_wch_hi[2048L * 2048],  g_wch_lo[2048L * 2048];
static __device__ __align__(128) __nv_bfloat16 g_wfc_hi[2048L * 2048],  g_wfc_lo[2048L * 2048];
static __device__ __align__(128) __nv_bfloat16 g_nh_hi[4096L * 2048],   g_nh_lo[4096L * 2048];
static __device__ __align__(128) __nv_bfloat16 g_lc_hi[4096L * 2048],   g_lc_lo[4096L * 2048];

__device__ __forceinline__ uint32_t s2u(const void* p) {
    uint32_t a;
    asm("{ .reg .u64 t; cvta.to.shared.u64 t, %1; cvt.u32.u64 %0, t; }" : "=r"(a) : "l"(p));
    return a;
}
#define CPA16(dst, src) \
    asm volatile("cp.async.cg.shared.global [%0], [%1], 16;" :: "r"(dst), "l"(src))

__device__ __forceinline__ void mma16816(float* d, const uint32_t* a, const uint32_t* b) {
    asm volatile(
        "mma.sync.aligned.m16n8k16.row.col.f32.bf16.bf16.f32 "
        "{%0,%1,%2,%3},{%4,%5,%6,%7},{%8,%9},{%0,%1,%2,%3};"
        : "+f"(d[0]), "+f"(d[1]), "+f"(d[2]), "+f"(d[3])
        : "r"(a[0]), "r"(a[1]), "r"(a[2]), "r"(a[3]), "r"(b[0]), "r"(b[1]));
}

__device__ __forceinline__ uint32_t pack_bf16x2(float x, float y) {
    __nv_bfloat162 t;
    t.x = __float2bfloat16(x);
    t.y = __float2bfloat16(y);
    return *reinterpret_cast<uint32_t*>(&t);
}
// split (v0,v1) into hi/lo bf16 pairs, store as packed u32
__device__ __forceinline__ void split2(float v0, float v1, uint32_t& hp, uint32_t& lp) {
    __nv_bfloat16 h0 = __float2bfloat16(v0), h1 = __float2bfloat16(v1);
    float l0 = v0 - __bfloat162float(h0), l1 = v1 - __bfloat162float(h1);
    __nv_bfloat162 hh; hh.x = h0; hh.y = h1;
    hp = *reinterpret_cast<uint32_t*>(&hh);
    lp = pack_bf16x2(l0, l1);
}

__device__ __forceinline__ void split_store4(float4 v, __nv_bfloat16* hi, __nv_bfloat16* lo, long idx) {
    __nv_bfloat16 h[4], l[4];
    float x[4] = {v.x, v.y, v.z, v.w};
#pragma unroll
    for (int i = 0; i < 4; ++i) {
        h[i] = __float2bfloat16(x[i]);
        l[i] = __float2bfloat16(x[i] - __bfloat162float(h[i]));
    }
    *reinterpret_cast<uint2*>(hi + idx) = *reinterpret_cast<const uint2*>(h);
    *reinterpret_cast<uint2*>(lo + idx) = *reinterpret_cast<const uint2*>(l);
}

// ---- conversion kernels (fp32 -> bf16 hi/lo) ----
__global__ __launch_bounds__(256) void conv_cat_k(
    const float* __restrict__ in, const float* __restrict__ hid,
    const float* __restrict__ ph, const float* __restrict__ ce,
    __nv_bfloat16* __restrict__ hi, __nv_bfloat16* __restrict__ lo)
{
    long g = (long)(blockIdx.x * 256 + threadIdx.x) * 4;
    int row = (int)(g / 7168), col = (int)(g % 7168);
    const float* p;
    if (col < 1024)      p = in  + (long)row * 1024 + col;
    else if (col < 3072) p = hid + (long)row * 2048 + (col - 1024);
    else if (col < 5120) p = ph  + (long)row * 2048 + (col - 3072);
    else                 p = ce  + (long)row * 2048 + (col - 5120);
    split_store4(*reinterpret_cast<const float4*>(p), hi, lo, g);
}

__global__ __launch_bounds__(256) void conv_w_k(
    const float* __restrict__ w, __nv_bfloat16* __restrict__ hi, __nv_bfloat16* __restrict__ lo)
{
    long g = (long)(blockIdx.x * 256 + threadIdx.x) * 4;
    split_store4(*reinterpret_cast<const float4*>(w + g), hi, lo, g);
}

// pad W_cm2 [100,7168] -> [128,7168] (zero rows 100..127)
__global__ __launch_bounds__(256) void conv_wpad_k(
    const float* __restrict__ w, __nv_bfloat16* __restrict__ hi, __nv_bfloat16* __restrict__ lo)
{
    long g = (long)(blockIdx.x * 256 + threadIdx.x) * 4;
    int row = (int)(g / 7168);
    float4 v = make_float4(0.f, 0.f, 0.f, 0.f);
    if (row < 100) v = *reinterpret_cast<const float4*>(w + g);
    split_store4(v, hi, lo, g);
}

// ---------------------------------------------------------------------------
// bf16x3 HMMA GEMM: C[M,N] = A[M,K] @ B[N,K]^T.
// CTA tile 128x128x32, 8 warps (4m x 2n), warp tile 32x64.
// 1D grid over (tilesM x tilesN) with GM=16 supergroup swizzle for L2 reuse.
// EPI: 0 = C=acc+bias; 1 = EPI0 + hi/lo(C); 2 = hi/lo(acc+bias+Cadd+biasv), no C;
//      3 = C=tanh(acc+bias); 4 = raw split-K plane store
// smem stage (40960 B): Ahi[0,10240) Alo[10240) Bhi[20480) Blo[30720); row stride 80 B.
// ---------------------------------------------------------------------------
template <int EPI>
__global__ __launch_bounds__(256, 2) void hgemm_k(
    int K, int kChunk, int tilesN,
    const __nv_bfloat16* __restrict__ Ahi, const __nv_bfloat16* __restrict__ Alo, int lda,
    const __nv_bfloat16* __restrict__ Bhi, const __nv_bfloat16* __restrict__ Blo,
    const float* __restrict__ bias, const float* __restrict__ Cadd,
    const float* __restrict__ biasv,
    float* __restrict__ C, int ldc,
    __nv_bfloat16* __restrict__ Ohi, __nv_bfloat16* __restrict__ Olo, int ldo)
{
    extern __shared__ char smem[];
    const uint32_t sbase = s2u(smem);
    const int tid = threadIdx.x;
    const int wid = tid >> 5, lane = tid & 31;
    const int g = lane >> 2, tig = lane & 3;
    const int warp_m = wid >> 1, warp_n = wid & 1;

    // ---- supergroup swizzle (GM=16 m-tiles per group) ----
    const int pid = blockIdx.x;
    const int tilesM = gridDim.x / tilesN;
    const int GM = 16;
    const int width = GM * tilesN;
    const int group_id = pid / width;
    const int first_m = group_id * GM;
    const int gsz = min(tilesM - first_m, GM);
    const int pid_m = first_m + (pid % gsz);
    const int pid_n = (pid % width) / gsz;

    const int m0 = pid_m * 128, n0 = pid_n * 128;
    const int kb = blockIdx.z * kChunk;
    if (EPI == 4) C += (long)blockIdx.z * (4096L * 128);

    float acc[2][8][4];
#pragma unroll
    for (int f = 0; f < 2; ++f)
#pragma unroll
        for (int j = 0; j < 8; ++j)
#pragma unroll
            for (int q = 0; q < 4; ++q) acc[f][j][q] = 0.f;

    auto issue = [&](int s, int kt) {
        const uint32_t st = sbase + (uint32_t)s * 40960u;
#pragma unroll
        for (int half = 0; half < 2; ++half) {
            int i = tid + half * 256;
            int r = i >> 2, c = i & 3;
            uint32_t dA = st + (uint32_t)(r * 80 + c * 16);
            long ga = (long)(m0 + r) * lda + kt + c * 8;
            CPA16(dA, Ahi + ga);
            CPA16(dA + 10240, Alo + ga);
            uint32_t dB = st + 20480u + (uint32_t)(r * 80 + c * 16);
            long gb = (long)(n0 + r) * (long)K + kt + c * 8;
            CPA16(dB, Bhi + gb);
            CPA16(dB + 10240, Blo + gb);
        }
        asm volatile("cp.async.commit_group;");
    };

    const int nt = kChunk / 32;
    issue(0, kb);

    for (int t = 0; t < nt; ++t) {
        if (t + 1 < nt) {
            issue((t + 1) & 1, kb + (t + 1) * 32);
            asm volatile("cp.async.wait_group 1;" ::: "memory");
        } else {
            asm volatile("cp.async.wait_group 0;" ::: "memory");
        }
        __syncthreads();

        const uint32_t st = sbase + (uint32_t)(t & 1) * 40960u;
        const uint32_t stA = st, stB = st + 20480u;

#pragma unroll
        for (int ks = 0; ks < 2; ++ks) {
            const int kbyte = ks * 32 + tig * 4;  // k elem = ks*16 + tig*2 -> bytes
            uint32_t aH[8], aL[8], b[16];

            // A hi fragments (2 m-frags x 4 regs)
#pragma unroll
            for (int f = 0; f < 2; ++f) {
                int r0 = warp_m * 32 + f * 16 + g;
                uint32_t base = stA + (uint32_t)(r0 * 80 + kbyte);
                aH[f * 4 + 0] = *(const uint32_t*)(smem + (base - sbase));
                aH[f * 4 + 1] = *(const uint32_t*)(smem + (base - sbase) + 8 * 80);
                aH[f * 4 + 2] = *(const uint32_t*)(smem + (base - sbase) + 16);
                aH[f * 4 + 3] = *(const uint32_t*)(smem + (base - sbase) + 8 * 80 + 16);
            }
            // B hi fragments (8 n-frags x 2 regs)
#pragma unroll
            for (int j = 0; j < 8; ++j) {
                int n = warp_n * 64 + j * 8 + g;
                uint32_t base = stB + (uint32_t)(n * 80 + kbyte);
                b[j * 2 + 0] = *(const uint32_t*)(smem + (base - sbase));
                b[j * 2 + 1] = *(const uint32_t*)(smem + (base - sbase) + 16);
            }
            // hh
#pragma unroll
            for (int f = 0; f < 2; ++f)
#pragma unroll
                for (int j = 0; j < 8; ++j) mma16816(acc[f][j], aH + f * 4, b + j * 2);

            // A lo fragments
#pragma unroll
            for (int f = 0; f < 2; ++f) {
                int r0 = warp_m * 32 + f * 16 + g;
                uint32_t base = stA + 10240u + (uint32_t)(r0 * 80 + kbyte);
                aL[f * 4 + 0] = *(const uint32_t*)(smem + (base - sbase));
                aL[f * 4 + 1] = *(const uint32_t*)(smem + (base - sbase) + 8 * 80);
                aL[f * 4 + 2] = *(const uint32_t*)(smem + (base - sbase) + 16);
                aL[f * 4 + 3] = *(const uint32_t*)(smem + (base - sbase) + 8 * 80 + 16);
            }
            // lh (aL * bH)
#pragma unroll
            for (int f = 0; f < 2; ++f)
#pragma unroll
                for (int j = 0; j < 8; ++j) mma16816(acc[f][j], aL + f * 4, b + j * 2);

            // B lo fragments (reuse b)
#pragma unroll
            for (int j = 0; j < 8; ++j) {
                int n = warp_n * 64 + j * 8 + g;
                uint32_t base = stB + 10240u + (uint32_t)(n * 80 + kbyte);
                b[j * 2 + 0] = *(const uint32_t*)(smem + (base - sbase));
                b[j * 2 + 1] = *(const uint32_t*)(smem + (base - sbase) + 16);
            }
            // hl (aH * bL)
#pragma unroll
            for (int f = 0; f < 2; ++f)
#pragma unroll
                for (int j = 0; j < 8; ++j) mma16816(acc[f][j], aH + f * 4, b + j * 2);
        }
        __syncthreads();
    }

    // ---- epilogue ----
#pragma unroll
    for (int f = 0; f < 2; ++f) {
#pragma unroll
        for (int j = 0; j < 8; ++j) {
            int row0 = m0 + warp_m * 32 + f * 16 + g;
            int col = n0 + warp_n * 64 + j * 8 + tig * 2;
#pragma unroll
            for (int h = 0; h < 2; ++h) {
                int row = row0 + h * 8;
                float v0 = acc[f][j][h * 2 + 0];
                float v1 = acc[f][j][h * 2 + 1];
                if constexpr (EPI == 4) {
                    *reinterpret_cast<float2*>(C + (long)row * ldc + col) = make_float2(v0, v1);
                } else {
                    float2 b2 = *reinterpret_cast<const float2*>(bias + col);
                    v0 += b2.x; v1 += b2.y;
                    if constexpr (EPI == 2) {
                        float2 a2 = *reinterpret_cast<const float2*>(Cadd + (long)row * 2048 + col);
                        float2 s2 = *reinterpret_cast<const float2*>(biasv + col);
                        v0 += a2.x + s2.x; v1 += a2.y + s2.y;
                        uint32_t hp, lp;
                        split2(v0, v1, hp, lp);
                        *reinterpret_cast<uint32_t*>(Ohi + (long)row * ldo + col) = hp;
                        *reinterpret_cast<uint32_t*>(Olo + (long)row * ldo + col) = lp;
                    } else if constexpr (EPI == 3) {
                        v0 = tanhf(v0); v1 = tanhf(v1);
                        *reinterpret_cast<float2*>(C + (long)row * ldc + col) = make_float2(v0, v1);
                    } else {
                        *reinterpret_cast<float2*>(C + (long)row * ldc + col) = make_float2(v0, v1);
                        if constexpr (EPI == 1) {
                            uint32_t hp, lp;
                            split2(v0, v1, hp, lp);
                            *reinterpret_cast<uint32_t*>(Ohi + (long)row * ldo + col) = hp;
                            *reinterpret_cast<uint32_t*>(Olo + (long)row * ldo + col) = lp;
                        }
                    }
                }
            }
        }
    }
}

// out = relu(mid) @ W_mo^T + b_mo; mid reduced from 16 split-K planes.
__global__ __launch_bounds__(256) void out_kernel(
    const float* __restrict__ midp, const float* __restrict__ b_cm2,
    const float* __restrict__ Wmo, const float* __restrict__ bmo,
    float* __restrict__ out)
{
    const int r0 = blockIdx.x * 8;
    const int n = threadIdx.x;
    __shared__ float sm[8][100];

    for (int idx = n; idx < 800; idx += 256) {
        int r = idx / 100;
        int k = idx - r * 100;
        float s = b_cm2[k];
#pragma unroll
        for (int p = 0; p < 16; ++p)
            s += midp[(long)p * (4096L * 128) + (long)(r0 + r) * 128 + k];
        sm[r][k] = fmaxf(s, 0.f);
    }
    __syncthreads();

    float acc[8];
#pragma unroll
    for (int r = 0; r < 8; ++r) acc[r] = 0.f;
    for (int k = 0; k < 100; ++k) {
        float w = Wmo[n * 100 + k];
#pragma unroll
        for (int r = 0; r < 8; ++r) acc[r] += sm[r][k] * w;
    }
    float bb = bmo[n];
#pragma unroll
    for (int r = 0; r < 8; ++r) out[(long)(r0 + r) * 256 + n] = acc[r] + bb;
}

// ---------------------------------------------------------------------------
extern "C" void kernel_launch(void* const* d_in, const int* in_sizes, int n_in,
                              void* d_out, int out_size)
{
    const float* input = (const float*)d_in[0];
    const float* hidden = (const float*)d_in[1];
    const float* prevh = (const float*)d_in[2];
    const float* cell = (const float*)d_in[3];
    const float* W_ch2 = (const float*)d_in[4];
    const float* b_ch2 = (const float*)d_in[5];
    const float* W_cm2 = (const float*)d_in[6];
    const float* b_cm2 = (const float*)d_in[7];
    const float* W_mo = (const float*)d_in[8];
    const float* b_mo = (const float*)d_in[9];
    const float* W_ci = (const float*)d_in[10];
    const float* b_ci = (const float*)d_in[11];
    const float* W_ch = (const float*)d_in[12];
    const float* b_ch = (const float*)d_in[13];
    const float* W_fc = (const float*)d_in[14];
    const float* b_fc = (const float*)d_in[15];
    const float* vbias = (const float*)d_in[16];
    (void)in_sizes; (void)n_in; (void)out_size;

    float* out = (float*)d_out;
    float* out_o = out;                  // [4096,256]
    float* out_nh = out + 1048576;       // new_hidden  [4096,2048]
    float* out_nc = out_nh + 8388608;    // new_cell    [4096,2048]
    float* out_ph = out_nc + 8388608;    // new_prev_hidden (= h_proj)

    float* midp;
    __nv_bfloat16 *cat_hi, *cat_lo, *wch2_hi, *wch2_lo, *wcm2_hi, *wcm2_lo;
    __nv_bfloat16 *wci_hi, *wci_lo, *wch_hi, *wch_lo, *wfc_hi, *wfc_lo;
    __nv_bfloat16 *nh_hi, *nh_lo, *lc_hi, *lc_lo;
    cudaGetSymbolAddress((void**)&midp, g_midp);
    cudaGetSymbolAddress((void**)&cat_hi, g_cat_hi);
    cudaGetSymbolAddress((void**)&cat_lo, g_cat_lo);
    cudaGetSymbolAddress((void**)&wch2_hi, g_wch2_hi);
    cudaGetSymbolAddress((void**)&wch2_lo, g_wch2_lo);
    cudaGetSymbolAddress((void**)&wcm2_hi, g_wcm2_hi);
    cudaGetSymbolAddress((void**)&wcm2_lo, g_wcm2_lo);
    cudaGetSymbolAddress((void**)&wci_hi, g_wci_hi);
    cudaGetSymbolAddress((void**)&wci_lo, g_wci_lo);
    cudaGetSymbolAddress((void**)&wch_hi, g_wch_hi);
    cudaGetSymbolAddress((void**)&wch_lo, g_wch_lo);
    cudaGetSymbolAddress((void**)&wfc_hi, g_wfc_hi);
    cudaGetSymbolAddress((void**)&wfc_lo, g_wfc_lo);
    cudaGetSymbolAddress((void**)&nh_hi, g_nh_hi);
    cudaGetSymbolAddress((void**)&nh_lo, g_nh_lo);
    cudaGetSymbolAddress((void**)&lc_hi, g_lc_hi);
    cudaGetSymbolAddress((void**)&lc_lo, g_lc_lo);

    const int SMEMSZ = 2 * 40960;  // 81920 B
    cudaFuncSetAttribute(hgemm_k<0>, cudaFuncAttributeMaxDynamicSharedMemorySize, SMEMSZ);
    cudaFuncSetAttribute(hgemm_k<1>, cudaFuncAttributeMaxDynamicSharedMemorySize, SMEMSZ);
    cudaFuncSetAttribute(hgemm_k<2>, cudaFuncAttributeMaxDynamicSharedMemorySize, SMEMSZ);
    cudaFuncSetAttribute(hgemm_k<3>, cudaFuncAttributeMaxDynamicSharedMemorySize, SMEMSZ);
    cudaFuncSetAttribute(hgemm_k<4>, cudaFuncAttributeMaxDynamicSharedMemorySize, SMEMSZ);

    // ---- conversions ----
    conv_cat_k<<<28672, 256>>>(input, hidden, prevh, cell, cat_hi, cat_lo);
    conv_w_k<<<14336, 256>>>(W_ch2, wch2_hi, wch2_lo);
    conv_wpad_k<<<896, 256>>>(W_cm2, wcm2_hi, wcm2_lo);
    conv_w_k<<<2048, 256>>>(W_ci, wci_hi, wci_lo);
    conv_w_k<<<4096, 256>>>(W_ch, wch_hi, wch_lo);
    conv_w_k<<<4096, 256>>>(W_fc, wfc_hi, wfc_lo);

    // L2: mid partials = concat @ W_cm2^T (split-K=16, N padded to 128)
    hgemm_k<4><<<dim3(32, 1, 16), 256, SMEMSZ>>>(
        7168, 448, 1, cat_hi, cat_lo, 7168, wcm2_hi, wcm2_lo,
        nullptr, nullptr, nullptr, midp, 128, nullptr, nullptr, 0);

    // L3: out = relu(mid) @ W_mo^T + b_mo
    out_kernel<<<512, 256>>>(midp, b_cm2, W_mo, b_mo, out_o);

    // L1: new_hidden = concat @ W_ch2^T + b_ch2  (+ hi/lo for L4)
    hgemm_k<1><<<dim3(512, 1, 1), 256, SMEMSZ>>>(
        7168, 7168, 16, cat_hi, cat_lo, 7168, wch2_hi, wch2_lo,
        b_ch2, nullptr, nullptr, out_nh, 2048, nh_hi, nh_lo, 2048);

    // L4: h_proj = new_hidden @ W_ch^T + b_ch -> new_prev_hidden
    hgemm_k<0><<<dim3(512, 1, 1), 256, SMEMSZ>>>(
        2048, 2048, 16, nh_hi, nh_lo, 2048, wch_hi, wch_lo,
        b_ch, nullptr, nullptr, out_ph, 2048, nullptr, nullptr, 0);

    // L5: lc = input @ W_ci^T + b_ci + h_proj + bias  (hi/lo only; A = first 1024 cols of concat)
    hgemm_k<2><<<dim3(512, 1, 1), 256, SMEMSZ>>>(
        1024, 1024, 16, cat_hi, cat_lo, 7168, wci_hi, wci_lo,
        b_ci, out_ph, vbias, nullptr, 0, lc_hi, lc_lo, 2048);

    // L6: new_cell = tanh(lc @ W_fc^T + b_fc)
    hgemm_k<3><<<dim3(512, 1, 1), 256, SMEMSZ>>>(
        2048, 2048, 16, lc_hi, lc_lo, 2048, wfc_hi, wfc_lo,
        b_fc, nullptr, nullptr, out_nc, 2048, nullptr, nullptr, 0);
}